// round 3
// baseline (speedup 1.0000x reference)
#include <cuda_runtime.h>

#define NN 100000
#define NE 1600000

// ---------------- scratch (static __device__ — allocation-free) ----------------
__device__ int    g_deg[NN];
__device__ int    g_cursor[NN];
__device__ int    g_rowptr[NN + 1];
__device__ int    g_bsum[256];
__device__ int    g_bsrc[NE];
__device__ float4 g_battr[NE];
__device__ float  g_xd[NN * 64];
__device__ float  g_xs[NN * 64];
__device__ float  g_cat0[NN * 96];      // layer0 concat input [x | s mean mx mn std]
__device__ float  g_big[NN * 384];      // layer1 concat input
__device__ float  g_h1[NN * 64];
__device__ float  g_h2[NN * 64];
__device__ float  g_hn[NN * 16];
__device__ float  g_gout[NN * 16];
// folded weights
__device__ float  g_Wc0[4 * 16],  g_xb0[16];
__device__ float  g_Wc1[4 * 64],  g_xb1[64];
__device__ float  g_Wcomb0[96 * 64],  g_bcomb0[64];
__device__ float  g_Wcomb1[384 * 64], g_bcomb1[64];

// ---------------- helpers ----------------
__global__ void k_zero() {
    int i = blockIdx.x * blockDim.x + threadIdx.x;
    if (i < NN) { g_deg[i] = 0; g_cursor[i] = 0; }
}

__global__ void k_count(const int* __restrict__ dst) {
    int e = blockIdx.x * blockDim.x + threadIdx.x;
    if (e < NE) atomicAdd(&g_deg[dst[e]], 1);
}

__global__ void k_scan1() {
    __shared__ int s[1024];
    int i = blockIdx.x * 1024 + threadIdx.x;
    int v = (i < NN) ? g_deg[i] : 0;
    s[threadIdx.x] = v;
    __syncthreads();
    for (int off = 1; off < 1024; off <<= 1) {
        int t = (threadIdx.x >= off) ? s[threadIdx.x - off] : 0;
        __syncthreads();
        s[threadIdx.x] += t;
        __syncthreads();
    }
    if (i < NN) g_rowptr[i] = s[threadIdx.x] - v;   // exclusive within block
    if (threadIdx.x == 1023) g_bsum[blockIdx.x] = s[1023];
}

__global__ void k_scan2(int nb) {
    __shared__ int s[256];
    int t = threadIdx.x;
    if (t < nb) s[t] = g_bsum[t];
    __syncthreads();
    if (t == 0) {
        int run = 0;
        for (int i = 0; i < nb; i++) { int v = s[i]; s[i] = run; run += v; }
    }
    __syncthreads();
    if (t < nb) g_bsum[t] = s[t];
}

__global__ void k_scan3() {
    int i = blockIdx.x * 1024 + threadIdx.x;
    if (i < NN) g_rowptr[i] += g_bsum[blockIdx.x];
    if (i == 0) g_rowptr[NN] = NE;
}

__global__ void k_scatter(const int* __restrict__ src, const int* __restrict__ dst,
                          const float* __restrict__ ea) {
    int e = blockIdx.x * blockDim.x + threadIdx.x;
    if (e >= NE) return;
    int d = dst[e];
    int p = g_rowptr[d] + atomicAdd(&g_cursor[d], 1);
    g_bsrc[p]  = src[e];
    g_battr[p] = ((const float4*)ea)[e];
}

// ---------------- weight folding ----------------
// Wc[i][f] = sum_j We[i][j] * Wpre[2F+j][f];  xb[f] = bpre[f] + sum_j be[j]*Wpre[2F+j][f]
__global__ void k_fold_edge(const float* __restrict__ We, const float* __restrict__ be,
                            const float* __restrict__ Wpre, const float* __restrict__ bpre,
                            int F, int layer) {
    int f = blockIdx.x * blockDim.x + threadIdx.x;
    if (f >= F) return;
    float a0 = 0, a1 = 0, a2 = 0, a3 = 0, b = bpre[f];
    for (int j = 0; j < F; j++) {
        float wv = Wpre[(2 * F + j) * F + f];
        a0 = fmaf(We[0 * F + j], wv, a0);
        a1 = fmaf(We[1 * F + j], wv, a1);
        a2 = fmaf(We[2 * F + j], wv, a2);
        a3 = fmaf(We[3 * F + j], wv, a3);
        b  = fmaf(be[j], wv, b);
    }
    float* Wc = layer ? g_Wc1 : g_Wc0;
    float* xb = layer ? g_xb1 : g_xb0;
    Wc[0 * F + f] = a0; Wc[1 * F + f] = a1; Wc[2 * F + f] = a2; Wc[3 * F + f] = a3;
    xb[f] = b;
}

// Wcomb[k][f] = sum_j Wpost[k][j]*Wlin[j][f];  bcomb = blin + bpost@Wlin
__global__ void k_fold_post(const float* __restrict__ Wpost, const float* __restrict__ bpost,
                            const float* __restrict__ Wlin, const float* __restrict__ blin,
                            int Kc, int layer) {
    int idx = blockIdx.x * blockDim.x + threadIdx.x;
    int total = Kc * 64;
    float* Wcomb = layer ? g_Wcomb1 : g_Wcomb0;
    float* bcomb = layer ? g_bcomb1 : g_bcomb0;
    if (idx < total) {
        int k = idx >> 6, f = idx & 63;
        float a = 0;
        for (int j = 0; j < 64; j++) a = fmaf(Wpost[k * 64 + j], Wlin[j * 64 + f], a);
        Wcomb[idx] = a;
    } else if (idx < total + 64) {
        int f = idx - total;
        float a = blin[f];
        for (int j = 0; j < 64; j++) a = fmaf(bpost[j], Wlin[j * 64 + f], a);
        bcomb[f] = a;
    }
}

// ---------------- layer-0 precompute: xd0/xs0 + copy x into cat0 ----------------
__global__ void k_xdxs0(const float* __restrict__ x, const float* __restrict__ Wpre0) {
    int t = blockIdx.x * blockDim.x + threadIdx.x;
    if (t >= NN * 32) return;
    int v = t >> 5, l = t & 31, f = l & 15;
    int rbase = (l < 16) ? 0 : 16;
    float acc = (l < 16) ? g_xb0[f] : 0.f;
    const float* xr = x + v * 16;
    #pragma unroll
    for (int j = 0; j < 16; j++)
        acc = fmaf(xr[j], Wpre0[(rbase + j) * 16 + f], acc);
    if (l < 16) { g_xd[v * 16 + f] = acc; g_cat0[v * 96 + f] = xr[f]; }
    else        { g_xs[v * 16 + f] = acc; }
}

// ---------------- PNA aggregation layer 0 (F=16, 16 lanes/node) ----------------
__global__ __launch_bounds__(256) void k_agg0() {
    int tid = threadIdx.x;
    int v = blockIdx.x * 16 + (tid >> 4);
    int f = tid & 15;
    if (v >= NN) return;
    int rs = g_rowptr[v], re = g_rowptr[v + 1];
    float xdv = g_xd[v * 16 + f];
    float w0 = g_Wc0[f], w1 = g_Wc0[16 + f], w2 = g_Wc0[32 + f], w3 = g_Wc0[48 + f];
    float s = 0, sq = 0, mx = -3.402823e38f, mn = 3.402823e38f;
    for (int e = rs; e < re; e++) {
        int sid = g_bsrc[e];
        float4 a = g_battr[e];
        float m = xdv + g_xs[sid * 16 + f];
        m = fmaf(a.x, w0, fmaf(a.y, w1, fmaf(a.z, w2, fmaf(a.w, w3, m))));
        s += m; sq = fmaf(m, m, sq); mx = fmaxf(mx, m); mn = fminf(mn, m);
    }
    int cnt = re - rs;
    float den = (float)(cnt > 0 ? cnt : 1);
    float mean = s / den, msq = sq / den;
    float sd = sqrtf(fmaxf(msq - mean * mean, 0.f) + 1e-5f);
    if (cnt == 0) { mx = 0.f; mn = 0.f; }
    float* o = g_cat0 + v * 96 + 16 + f;
    o[0] = s; o[16] = mean; o[32] = mx; o[48] = mn; o[64] = sd;
}

// ---------------- PNA aggregation layer 1 (F=64, 64 lanes/node) ----------------
__global__ __launch_bounds__(256) void k_agg1() {
    int tid = threadIdx.x;
    int v = blockIdx.x * 4 + (tid >> 6);
    int f = tid & 63;
    if (v >= NN) return;
    int rs = g_rowptr[v], re = g_rowptr[v + 1];
    float xdv = g_xd[v * 64 + f];
    float w0 = g_Wc1[f], w1 = g_Wc1[64 + f], w2 = g_Wc1[128 + f], w3 = g_Wc1[192 + f];
    float s = 0, sq = 0, mx = -3.402823e38f, mn = 3.402823e38f;
    for (int e = rs; e < re; e++) {
        int sid = g_bsrc[e];
        float4 a = g_battr[e];
        float m = xdv + g_xs[sid * 64 + f];
        m = fmaf(a.x, w0, fmaf(a.y, w1, fmaf(a.z, w2, fmaf(a.w, w3, m))));
        s += m; sq = fmaf(m, m, sq); mx = fmaxf(mx, m); mn = fminf(mn, m);
    }
    int cnt = re - rs;
    float den = (float)(cnt > 0 ? cnt : 1);
    float mean = s / den, msq = sq / den;
    float sd = sqrtf(fmaxf(msq - mean * mean, 0.f) + 1e-5f);
    if (cnt == 0) { mx = 0.f; mn = 0.f; }
    float* o = g_big + v * 384 + 64 + f;
    o[0] = s; o[64] = mean; o[128] = mx; o[192] = mn; o[256] = sd;
}

// ---------------- tiled fp32 GEMM: C[M,64] = A[M,K] @ W[K,64] (+bias)(+relu) ----------------
template<int K, bool RELU>
__global__ __launch_bounds__(256) void k_gemm64(
    const float* __restrict__ A, int lda,
    const float* __restrict__ W,
    const float* __restrict__ bias,
    float* __restrict__ C, int ldc,
    float* __restrict__ C2, int ldc2,
    int M)
{
    __shared__ float As[16][68];
    __shared__ float Bs[16][64];
    int tid = threadIdx.x;
    int tx = tid & 15, ty = tid >> 4;          // col group, row group
    int rowBase = blockIdx.x * 64;
    float acc[4][4];
    #pragma unroll
    for (int i = 0; i < 4; i++)
        #pragma unroll
        for (int j = 0; j < 4; j++) acc[i][j] = 0.f;

    int ka = tid & 15, ra = tid >> 4;          // A-load mapping
    int cb = tid & 63, kb = tid >> 6;          // B-load mapping

    for (int kc = 0; kc < K; kc += 16) {
        #pragma unroll
        for (int i = 0; i < 4; i++) {
            int r = ra + i * 16;
            int gr = rowBase + r;
            As[ka][r] = (gr < M) ? A[gr * lda + kc + ka] : 0.f;
        }
        #pragma unroll
        for (int i = 0; i < 4; i++)
            Bs[kb + i * 4][cb] = W[(kc + kb + i * 4) * 64 + cb];
        __syncthreads();
        #pragma unroll
        for (int k = 0; k < 16; k++) {
            float4 b4 = *(const float4*)&Bs[k][tx * 4];
            float4 a4 = *(const float4*)&As[k][ty * 4];
            float av[4] = {a4.x, a4.y, a4.z, a4.w};
            float bv[4] = {b4.x, b4.y, b4.z, b4.w};
            #pragma unroll
            for (int i = 0; i < 4; i++)
                #pragma unroll
                for (int j = 0; j < 4; j++)
                    acc[i][j] = fmaf(av[i], bv[j], acc[i][j]);
        }
        __syncthreads();
    }

    int c0 = tx * 4;
    float bv[4];
    #pragma unroll
    for (int j = 0; j < 4; j++) bv[j] = bias ? bias[c0 + j] : 0.f;
    #pragma unroll
    for (int i = 0; i < 4; i++) {
        int gr = rowBase + ty * 4 + i;
        if (gr < M) {
            float4 o;
            float* po = (float*)&o;
            #pragma unroll
            for (int j = 0; j < 4; j++) {
                float v = acc[i][j] + bv[j];
                if (RELU) v = fmaxf(v, 0.f);
                po[j] = v;
            }
            *(float4*)&C[gr * ldc + c0] = o;
            if (C2) *(float4*)&C2[gr * ldc2 + c0] = o;
        }
    }
}

// ---------------- GCN ----------------
__global__ __launch_bounds__(256) void k_gcn_hn(const float* __restrict__ Wg) {
    __shared__ float w[64 * 16];
    int tid = threadIdx.x;
    for (int i = tid; i < 1024; i += 256) w[i] = Wg[i];
    __syncthreads();
    int v = blockIdx.x * 16 + (tid >> 4);
    int f = tid & 15;
    if (v >= NN) return;
    const float* h = g_h2 + v * 64;
    float acc = 0;
    #pragma unroll 8
    for (int j = 0; j < 64; j++) acc = fmaf(h[j], w[j * 16 + f], acc);
    float dinv = rsqrtf((float)(g_deg[v] + 1));
    g_hn[v * 16 + f] = acc * dinv;
}

__global__ __launch_bounds__(256) void k_gcn_agg(const float* __restrict__ bg) {
    int tid = threadIdx.x;
    int v = blockIdx.x * 16 + (tid >> 4);
    int f = tid & 15;
    if (v >= NN) return;
    int rs = g_rowptr[v], re = g_rowptr[v + 1];
    float s = g_hn[v * 16 + f];                 // self loop term
    for (int e = rs; e < re; e++)
        s += g_hn[g_bsrc[e] * 16 + f];
    float dinv = rsqrtf((float)(g_deg[v] + 1));
    g_gout[v * 16 + f] = s * dinv + bg[f];
}

// ---------------- head ----------------
__global__ __launch_bounds__(256) void k_head(
    const float* __restrict__ x,
    const float* __restrict__ Wh1, const float* __restrict__ bh1,
    const float* __restrict__ Wh2, const float* __restrict__ bh2,
    float* __restrict__ out)
{
    __shared__ float w1[320], b1[10], w2[100], b2[10];
    int tid = threadIdx.x;
    for (int i = tid; i < 320; i += 256) w1[i] = Wh1[i];
    for (int i = tid; i < 100; i += 256) w2[i] = Wh2[i];
    if (tid < 10) { b1[tid] = bh1[tid]; b2[tid] = bh2[tid]; }
    __syncthreads();
    int v = blockIdx.x * 256 + tid;
    if (v >= NN) return;
    float z[32];
    #pragma unroll
    for (int j = 0; j < 16; j++) {
        z[j]      = g_gout[v * 16 + j];
        z[16 + j] = x[v * 16 + j];
    }
    float t[10];
    #pragma unroll
    for (int j = 0; j < 10; j++) {
        float a = b1[j];
        #pragma unroll
        for (int i = 0; i < 32; i++) a = fmaf(z[i], w1[i * 10 + j], a);
        t[j] = fmaxf(a, 0.f);
    }
    #pragma unroll
    for (int j = 0; j < 10; j++) {
        float a = b2[j];
        #pragma unroll
        for (int k = 0; k < 10; k++) a = fmaf(t[k], w2[k * 10 + j], a);
        out[v * 10 + j] = a;
    }
}

// ---------------- driver ----------------
extern "C" void kernel_launch(void* const* d_in, const int* in_sizes, int n_in,
                              void* d_out, int out_size) {
    const float* x     = (const float*)d_in[0];
    const int*   ei    = (const int*)  d_in[1];
    const float* ea    = (const float*)d_in[2];
    const float* We0   = (const float*)d_in[3];
    const float* be0   = (const float*)d_in[4];
    const float* Wpre0 = (const float*)d_in[5];
    const float* bpre0 = (const float*)d_in[6];
    const float* Wpost0= (const float*)d_in[7];
    const float* bpost0= (const float*)d_in[8];
    const float* Wlin0 = (const float*)d_in[9];
    const float* blin0 = (const float*)d_in[10];
    const float* We1   = (const float*)d_in[11];
    const float* be1   = (const float*)d_in[12];
    const float* Wpre1 = (const float*)d_in[13];
    const float* bpre1 = (const float*)d_in[14];
    const float* Wpost1= (const float*)d_in[15];
    const float* bpost1= (const float*)d_in[16];
    const float* Wlin1 = (const float*)d_in[17];
    const float* blin1 = (const float*)d_in[18];
    const float* Wg    = (const float*)d_in[19];
    const float* bg    = (const float*)d_in[20];
    const float* Wh1   = (const float*)d_in[21];
    const float* bh1   = (const float*)d_in[22];
    const float* Wh2   = (const float*)d_in[23];
    const float* bh2   = (const float*)d_in[24];
    float* out = (float*)d_out;

    const int* srcp = ei;
    const int* dstp = ei + NE;

    // device symbol addresses (query-only API, capture-safe)
    float *p_cat0, *p_big, *p_h1, *p_h2, *p_xd, *p_xs;
    float *p_Wcomb0, *p_bcomb0, *p_Wcomb1, *p_bcomb1, *p_xb1;
    cudaGetSymbolAddress((void**)&p_cat0,  g_cat0);
    cudaGetSymbolAddress((void**)&p_big,   g_big);
    cudaGetSymbolAddress((void**)&p_h1,    g_h1);
    cudaGetSymbolAddress((void**)&p_h2,    g_h2);
    cudaGetSymbolAddress((void**)&p_xd,    g_xd);
    cudaGetSymbolAddress((void**)&p_xs,    g_xs);
    cudaGetSymbolAddress((void**)&p_Wcomb0,g_Wcomb0);
    cudaGetSymbolAddress((void**)&p_bcomb0,g_bcomb0);
    cudaGetSymbolAddress((void**)&p_Wcomb1,g_Wcomb1);
    cudaGetSymbolAddress((void**)&p_bcomb1,g_bcomb1);
    cudaGetSymbolAddress((void**)&p_xb1,   g_xb1);

    const int EB = (NE + 255) / 256;           // 6250
    const int SB = (NN + 1023) / 1024;         // 98
    const int GB = (NN + 63) / 64;             // 1563

    // CSR build
    k_zero<<<(NN + 255) / 256, 256>>>();
    k_count<<<EB, 256>>>(dstp);
    k_scan1<<<SB, 1024>>>();
    k_scan2<<<1, 256>>>(SB);
    k_scan3<<<SB, 1024>>>();
    k_scatter<<<EB, 256>>>(srcp, dstp, ea);

    // weight folding (independent of CSR)
    k_fold_edge<<<1, 64>>>(We0, be0, Wpre0, bpre0, 16, 0);
    k_fold_edge<<<1, 64>>>(We1, be1, Wpre1, bpre1, 64, 1);
    k_fold_post<<<(96 * 64 + 64 + 255) / 256, 256>>>(Wpost0, bpost0, Wlin0, blin0, 96, 0);
    k_fold_post<<<(384 * 64 + 64 + 255) / 256, 256>>>(Wpost1, bpost1, Wlin1, blin1, 384, 1);

    // PNA layer 0
    k_xdxs0<<<(NN * 32 + 255) / 256, 256>>>(x, Wpre0);
    k_agg0<<<(NN + 15) / 16, 256>>>();
    // h1 = relu(cat0 @ Wcomb0 + bcomb0); also write h1 into big[:, 0:64]
    k_gemm64<96, true><<<GB, 256>>>(p_cat0, 96, p_Wcomb0, p_bcomb0,
                                    p_h1, 64, p_big, 384, NN);

    // PNA layer 1
    k_gemm64<64, false><<<GB, 256>>>(p_h1, 64, Wpre1, p_xb1,
                                     p_xd, 64, (float*)nullptr, 0, NN);        // xd1
    k_gemm64<64, false><<<GB, 256>>>(p_h1, 64, Wpre1 + 64 * 64, (float*)nullptr,
                                     p_xs, 64, (float*)nullptr, 0, NN);        // xs1
    k_agg1<<<(NN + 3) / 4, 256>>>();
    k_gemm64<384, true><<<GB, 256>>>(p_big, 384, p_Wcomb1, p_bcomb1,
                                     p_h2, 64, (float*)nullptr, 0, NN);

    // GCN
    k_gcn_hn<<<(NN + 15) / 16, 256>>>(Wg);
    k_gcn_agg<<<(NN + 15) / 16, 256>>>(bg);

    // head
    k_head<<<(NN + 255) / 256, 256>>>(x, Wh1, bh1, Wh2, bh2, out);
}